// round 14
// baseline (speedup 1.0000x reference)
#include <cuda_runtime.h>
#include <cuda_fp16.h>
#include <cstdint>
#include <cstddef>

// ---------------- problem dims ----------------
#define B_SZ 16
#define T_SZ 2048
#define K_IN 1024
#define D_MODEL 1024
#define MLP 2048
#define NCLS 1000

// ---------------- GEMM tiling ----------------
#define BM 128               // t-rows per block (scan chunk)
#define BK 64                // k per pipeline chunk
#define NCH (K_IN / BK)      // 16
#define NCHUNK (T_SZ / BM)   // 16
#define NSTAGE 3

#define ROWB 128                 // bytes per smem row (64 halves, swizzled)
#define ABYTES (BM * ROWB)       // 16384
#define STAGE (2 * ABYTES)       // 32768 (A + W)
#define EPITCH 66                // epilogue float pitch
#define SMEM_TOTAL (NSTAGE * STAGE)   // 98304; epilogue needs 67584, fits

// ---------------- scratch ----------------
__device__ __align__(16) __half g_xh[(size_t)B_SZ * T_SZ * K_IN];   // 64 MB
__device__ __align__(16) __half g_wh[2048 * K_IN];                  // 4 MB, [n][k]
__device__ float g_chunkA[B_SZ * NCHUNK * D_MODEL];
__device__ float g_chunkC[B_SZ * NCHUNK * D_MODEL];
__device__ float g_h[B_SZ * D_MODEL];
__device__ float g_opre[B_SZ * D_MODEL];
__device__ float g_n0pre[B_SZ * MLP];
__device__ float g_n1pre[B_SZ * MLP];

// ---------------- helpers ----------------
__device__ __forceinline__ uint32_t smem_u32(const void* p) {
    uint32_t a;
    asm("{ .reg .u64 t; cvta.to.shared.u64 t, %1; cvt.u32.u64 %0, t; }" : "=r"(a) : "l"(p));
    return a;
}
__device__ __forceinline__ void cpa16(uint32_t dst, const void* src) {
    asm volatile("cp.async.cg.shared.global [%0], [%1], 16;\n" :: "r"(dst), "l"(src));
}
#define CP_COMMIT() asm volatile("cp.async.commit_group;" ::: "memory")
#define CP_WAIT(n) asm volatile("cp.async.wait_group %0;" :: "n"(n) : "memory")

__device__ __forceinline__ void ldm4(uint32_t r[4], uint32_t addr) {
    asm volatile("ldmatrix.sync.aligned.m8n8.x4.shared.b16 {%0,%1,%2,%3}, [%4];"
                 : "=r"(r[0]), "=r"(r[1]), "=r"(r[2]), "=r"(r[3]) : "r"(addr));
}

__device__ __forceinline__ void mma_f16(float c[4],
                                        uint32_t a0, uint32_t a1, uint32_t a2, uint32_t a3,
                                        uint32_t b0, uint32_t b1) {
    asm volatile(
        "mma.sync.aligned.m16n8k16.row.col.f32.f16.f16.f32 "
        "{%0,%1,%2,%3}, {%4,%5,%6,%7}, {%8,%9}, {%0,%1,%2,%3};\n"
        : "+f"(c[0]), "+f"(c[1]), "+f"(c[2]), "+f"(c[3])
        : "r"(a0), "r"(a1), "r"(a2), "r"(a3), "r"(b0), "r"(b1));
}

__device__ __forceinline__ float tanh_fast(float x) {
    float r;
    asm("tanh.approx.f32 %0, %1;" : "=f"(r) : "f"(x));
    return r;
}
__device__ __forceinline__ float sigmoid_fast(float x) {
    return fmaf(tanh_fast(0.5f * x), 0.5f, 0.5f);
}
__device__ __forceinline__ float sigmoidf_(float x) { return 1.0f / (1.0f + __expf(-x)); }

// =====================================================================
// convx + zero scratch + init d_out with b2 (fused)
// =====================================================================
__global__ void convx_kernel(const float* __restrict__ x,
                             const float* __restrict__ b2,
                             float* __restrict__ out) {
    size_t n4 = (size_t)B_SZ * T_SZ * K_IN / 4;
    for (size_t i = blockIdx.x * 256 + threadIdx.x; i < n4; i += (size_t)gridDim.x * 256) {
        float4 v = ((const float4*)x)[i];
        __half2* o = (__half2*)g_xh;
        o[i * 2] = __floats2half2_rn(v.x, v.y);
        o[i * 2 + 1] = __floats2half2_rn(v.z, v.w);
    }
    int zi = blockIdx.x * 256 + threadIdx.x;
    if (zi < B_SZ * D_MODEL) g_opre[zi] = 0.0f;
    if (zi < B_SZ * MLP) { g_n0pre[zi] = 0.0f; g_n1pre[zi] = 0.0f; }
    if (zi < B_SZ * NCLS) out[zi] = b2[zi % NCLS];
}

// transpose Wp[:, 0:2048] -> g_wh[n][k] fp16
__global__ void __launch_bounds__(256) convw_kernel(const float* __restrict__ Wp) {
    __shared__ float tile[64][65];
    int k0 = blockIdx.x * 64;
    int n0 = blockIdx.y * 64;
    int tid = threadIdx.x;
#pragma unroll
    for (int i = 0; i < 16; i++) {
        int idx = tid + i * 256;
        int r = idx >> 6, c = idx & 63;
        tile[r][c] = Wp[(size_t)(k0 + r) * 3072 + n0 + c];
    }
    __syncthreads();
#pragma unroll
    for (int i = 0; i < 16; i++) {
        int idx = tid + i * 256;
        int r = idx >> 6, c = idx & 63;
        g_wh[(size_t)(n0 + r) * K_IN + k0 + c] = __float2half(tile[c][r]);
    }
}

// =====================================================================
// Fused fp16 mma.sync GEMM: swizzled ldmatrix, 3-stage cp.async,
// fully-unrolled chunk loop (compile-time stage indices), ONE barrier
// per chunk with load issued right after it. + activations + scan.
// Grid: (16 d-tiles, 256 bc). Block: 256 threads (8 warps, 2x4).
// =====================================================================
__global__ void __launch_bounds__(256)
gemm_scan_kernel(const float* __restrict__ bp) {
    extern __shared__ char smem[];
    const uint32_t sb = smem_u32(smem);

    const int dt = blockIdx.x;
    const int bc = blockIdx.y;
    const int b = bc >> 4;
    const int chunk = bc & 15;
    const int d0 = dt * 64;

    const int tid = threadIdx.x;
    const int lane = tid & 31;
    const int wid = tid >> 5;
    const int wm = (wid >> 2) * 64;       // warp m offset (0/64)
    const int wn = (wid & 3) * 32;        // warp n offset (0..96)
    const int g = lane >> 2;
    const int tg = lane & 3;

    const __half* xbase = g_xh + ((size_t)(b * T_SZ + chunk * BM)) * K_IN;

    float acc[4][4][4];
#pragma unroll
    for (int mi = 0; mi < 4; mi++)
#pragma unroll
        for (int ni = 0; ni < 4; ni++)
#pragma unroll
            for (int r = 0; r < 4; r++) acc[mi][ni][r] = 0.0f;

    // ldmatrix lane geometry (swizzled 128B rows)
    const int aRow = wm + (lane & 15);
    const int aHi = (lane >> 4) & 1;
    const int aSw = aRow & 7;
    const int bRow = wn + ((lane >> 4) & 1) * 8 + (lane & 7);
    const int bHi = (lane >> 3) & 1;
    const int bSw = lane & 7;

    auto load_stage = [&](int s, int kk) {
        uint32_t abase = sb + s * STAGE;
        uint32_t wbase = abase + ABYTES;
#pragma unroll
        for (int j = 0; j < 4; j++) {
            int idx = tid + j * 256;
            int r = idx >> 3, c8 = idx & 7;
            cpa16(abase + r * ROWB + ((c8 ^ (r & 7)) << 4),
                  xbase + (size_t)r * K_IN + kk + c8 * 8);
        }
#pragma unroll
        for (int j = 0; j < 4; j++) {
            int idx = tid + j * 256;
            int n = idx >> 3, c8 = idx & 7;
            int grow = (n < 64) ? (d0 + n) : (960 + d0 + n);
            cpa16(wbase + n * ROWB + ((c8 ^ (n & 7)) << 4),
                  g_wh + (size_t)grow * K_IN + kk + c8 * 8);
        }
        CP_COMMIT();
    };

    load_stage(0, 0);
    load_stage(1, BK);

#pragma unroll
    for (int i = 0; i < NCH; i++) {
        const int s = i % NSTAGE;               // compile-time (full unroll)
        if (i < NCH - 1) { CP_WAIT(1); } else { CP_WAIT(0); }
        __syncthreads();   // stage s complete AND buffer (i+2)%3 free
        if (i + 2 < NCH) load_stage((i + 2) % NSTAGE, (i + 2) * BK);

        const uint32_t stage = sb + s * STAGE;
        const uint32_t bstage = stage + ABYTES;
#pragma unroll
        for (int ks = 0; ks < BK / 16; ks++) {
            uint32_t a[4][4];
#pragma unroll
            for (int mi = 0; mi < 4; mi++)
                ldm4(a[mi], stage + (aRow + mi * 16) * ROWB +
                            ((((ks * 2 + aHi)) ^ aSw) << 4));
            uint32_t bb[4][2];
#pragma unroll
            for (int p = 0; p < 2; p++) {
                uint32_t r[4];
                ldm4(r, bstage + (bRow + p * 16) * ROWB +
                        ((((ks * 2 + bHi)) ^ bSw) << 4));
                bb[2 * p][0] = r[0]; bb[2 * p][1] = r[1];
                bb[2 * p + 1][0] = r[2]; bb[2 * p + 1][1] = r[3];
            }
#pragma unroll
            for (int mi = 0; mi < 4; mi++)
#pragma unroll
                for (int ni = 0; ni < 4; ni++)
                    mma_f16(acc[mi][ni], a[mi][0], a[mi][1], a[mi][2], a[mi][3],
                            bb[ni][0], bb[ni][1]);
        }
    }
    __syncthreads();   // all stage reads done before epilogue overwrite

    // ---- epilogue: accumulators -> smem (f | z), then chunk scan ----
    float* fS = (float*)smem;                       // [128][EPITCH]
    float* zS = (float*)smem + 128 * EPITCH;        // [128][EPITCH]

#pragma unroll
    for (int mi = 0; mi < 4; mi++) {
#pragma unroll
        for (int ni = 0; ni < 4; ni++) {
            int nc = wn + ni * 8 + tg * 2;          // 0..126
            float* buf = (nc < 64) ? fS : zS;
            int col = nc & 63;
            int r = wm + mi * 16 + g;
            *(float2*)&buf[r * EPITCH + col] = make_float2(acc[mi][ni][0], acc[mi][ni][1]);
            *(float2*)&buf[(r + 8) * EPITCH + col] = make_float2(acc[mi][ni][2], acc[mi][ni][3]);
        }
    }
    __syncthreads();

    {
        const int dd = tid & 63;
        const int j = tid >> 6;                      // 4 t-subchunks of 32
        const float bpf = bp[d0 + dd];
        const float bpz = bp[D_MODEL + d0 + dd];
        float A = 1.0f, C = 0.0f;
#pragma unroll 4
        for (int t = j * 32; t < j * 32 + 32; t++) {
            float fh = fS[t * EPITCH + dd] + bpf;
            float zh = zS[t * EPITCH + dd] + bpz;
            float f = sigmoid_fast(fh);
            float z = (1.0f - f) * tanh_fast(zh);
            C = C * f + z;
            A = A * f;
        }
        __shared__ float s4A[4][64];
        __shared__ float s4C[4][64];
        s4A[j][dd] = A;
        s4C[j][dd] = C;
        __syncthreads();
        if (tid < 64) {
            float AA = s4A[0][tid], CC = s4C[0][tid];
#pragma unroll
            for (int jj = 1; jj < 4; jj++) {
                CC = CC * s4A[jj][tid] + s4C[jj][tid];
                AA = AA * s4A[jj][tid];
            }
            size_t o = ((size_t)b * NCHUNK + chunk) * D_MODEL + d0 + tid;
            g_chunkA[o] = AA;
            g_chunkC[o] = CC;
        }
    }
}

// =====================================================================
// combine chunks -> c_T, then h = c_T * sigmoid(opre + bp_o)  (fused)
// =====================================================================
__global__ void combine_oh_kernel(const float* __restrict__ bp) {
    int b = blockIdx.y;
    int d = blockIdx.x * 256 + threadIdx.x;
    float c = 0.0f;
#pragma unroll
    for (int ch = 0; ch < NCHUNK; ch++) {
        size_t o = ((size_t)b * NCHUNK + ch) * D_MODEL + d;
        c = c * g_chunkA[o] + g_chunkC[o];
    }
    int i = b * D_MODEL + d;
    float o = sigmoidf_(g_opre[i] + bp[2 * D_MODEL + d]);
    g_h[i] = c * o;
}

// =====================================================================
// Tail: split-K vector(16) x matrix + atomicAdd.
// Optional bias+ReLU on the INPUT at load time.
// =====================================================================
#define KS 32
__global__ void __launch_bounds__(256)
vmacc_kernel(const float* __restrict__ in, size_t inStride,
             const float* __restrict__ inBias,      // nullptr = no act
             const float* __restrict__ W, int ldw, int colOff,
             float* __restrict__ pre, int K, int N) {
    __shared__ float s_in[B_SZ * KS];
    const int tid = threadIdx.x;
    const int bn = blockIdx.x * 256;
    const int ks = blockIdx.y * KS;

    for (int i = tid; i < B_SZ * KS; i += 256) {
        int bb = i / KS, k = i % KS;
        float v = in[(size_t)bb * inStride + ks + k];
        if (inBias) {
            v += inBias[ks + k];
            v = v > 0.0f ? v : 0.0f;
        }
        s_in[i] = v;
    }
    __syncthreads();

    int n = bn + tid;
    if (n >= N) return;

    float acc[B_SZ];
#pragma unroll
    for (int bb = 0; bb < B_SZ; bb++) acc[bb] = 0.0f;

#pragma unroll 4
    for (int k = 0; k < KS; k++) {
        float w = W[(size_t)(ks + k) * ldw + colOff + n];
#pragma unroll
        for (int bb = 0; bb < B_SZ; bb++) acc[bb] += s_in[bb * KS + k] * w;
    }
#pragma unroll
    for (int bb = 0; bb < B_SZ; bb++) atomicAdd(&pre[(size_t)bb * N + n], acc[bb]);
}

// =====================================================================
extern "C" void kernel_launch(void* const* d_in, const int* in_sizes, int n_in,
                              void* d_out, int out_size) {
    const float* x  = (const float*)d_in[0];
    const float* Wp = (const float*)d_in[1];
    const float* bp = (const float*)d_in[2];
    const float* W0 = (const float*)d_in[3];
    const float* b0 = (const float*)d_in[4];
    const float* W1 = (const float*)d_in[5];
    const float* b1 = (const float*)d_in[6];
    const float* W2 = (const float*)d_in[7];
    const float* b2 = (const float*)d_in[8];
    float* out = (float*)d_out;

    cudaFuncSetAttribute(gemm_scan_kernel,
                         cudaFuncAttributeMaxDynamicSharedMemorySize, SMEM_TOTAL);

    float *p_h, *p_opre, *p_n0pre, *p_n1pre;
    cudaGetSymbolAddress((void**)&p_h, g_h);
    cudaGetSymbolAddress((void**)&p_opre, g_opre);
    cudaGetSymbolAddress((void**)&p_n0pre, g_n0pre);
    cudaGetSymbolAddress((void**)&p_n1pre, g_n1pre);

    // 0. conversions (+ scratch zeroing + d_out=b2 folded into convx)
    convx_kernel<<<2048, 256>>>(x, b2, out);
    convw_kernel<<<dim3(K_IN / 64, 2048 / 64), 256>>>(Wp);

    // 1. o-projection at t = T-1 (independent of the big GEMM)
    vmacc_kernel<<<dim3(D_MODEL / 256, K_IN / KS), 256>>>(
        x + (size_t)(T_SZ - 1) * K_IN, (size_t)T_SZ * K_IN, nullptr,
        Wp, 3 * D_MODEL, 2 * D_MODEL, p_opre, K_IN, D_MODEL);

    // 2. fused fp16 GEMM + chunk scan
    gemm_scan_kernel<<<dim3(16, B_SZ * NCHUNK), 256, SMEM_TOTAL>>>(bp);

    // 3. combine chunks -> c_T -> h (fused with o gate)
    combine_oh_kernel<<<dim3(D_MODEL / 256, B_SZ), 256>>>(bp);

    // 4. MLP layer 0: n0pre = h @ W0
    vmacc_kernel<<<dim3(MLP / 256, D_MODEL / KS), 256>>>(
        p_h, D_MODEL, nullptr, W0, MLP, 0, p_n0pre, D_MODEL, MLP);

    // 5. MLP layer 1: n1pre = relu(n0pre + b0) @ W1   (act fused into load)
    vmacc_kernel<<<dim3(MLP / 256, MLP / KS), 256>>>(
        p_n0pre, MLP, b0, W1, MLP, 0, p_n1pre, MLP, MLP);

    // 6. output: out = b2 + relu(n1pre + b1) @ W2     (direct atomicAdd into d_out)
    vmacc_kernel<<<dim3((NCLS + 255) / 256, MLP / KS), 256>>>(
        p_n1pre, MLP, b1, W2, NCLS, 0, out, MLP, NCLS);
}

// round 15
// speedup vs baseline: 1.3953x; 1.3953x over previous
#include <cuda_runtime.h>
#include <cuda_fp16.h>
#include <cstdint>
#include <cstddef>

// ---------------- problem dims ----------------
#define B_SZ 16
#define T_SZ 2048
#define K_IN 1024
#define D_MODEL 1024
#define MLP 2048
#define NCLS 1000

// ---------------- GEMM tiling ----------------
#define BM 128               // t-rows per block (scan chunk)
#define BK 64                // k per pipeline chunk
#define NCH (K_IN / BK)      // 16
#define NCHUNK (T_SZ / BM)   // 16

#define ROWB 128                 // bytes per smem row (64 halves, swizzled)
#define ABYTES (BM * ROWB)       // 16384
#define STAGE (2 * ABYTES)       // 32768 (A + W)
#define EPITCH 66                // epilogue float pitch
#define SMEM_TOTAL (2 * 128 * EPITCH * 4)   // 67584 (> 2*STAGE = 65536)

// ---------------- scratch ----------------
__device__ __align__(16) __half g_xh[(size_t)B_SZ * T_SZ * K_IN];   // 64 MB
__device__ __align__(16) __half g_wh[2048 * K_IN];                  // 4 MB, [n][k]
__device__ float g_chunkA[B_SZ * NCHUNK * D_MODEL];
__device__ float g_chunkC[B_SZ * NCHUNK * D_MODEL];
__device__ float g_opre[B_SZ * D_MODEL];
__device__ float g_n0pre[B_SZ * MLP];
__device__ float g_n1pre[B_SZ * MLP];

// ---------------- helpers ----------------
__device__ __forceinline__ uint32_t smem_u32(const void* p) {
    uint32_t a;
    asm("{ .reg .u64 t; cvta.to.shared.u64 t, %1; cvt.u32.u64 %0, t; }" : "=r"(a) : "l"(p));
    return a;
}
__device__ __forceinline__ void cpa16(uint32_t dst, const void* src) {
    asm volatile("cp.async.cg.shared.global [%0], [%1], 16;\n" :: "r"(dst), "l"(src));
}
#define CP_COMMIT() asm volatile("cp.async.commit_group;" ::: "memory")
#define CP_WAIT(n) asm volatile("cp.async.wait_group %0;" :: "n"(n) : "memory")

__device__ __forceinline__ void ldm4(uint32_t r[4], uint32_t addr) {
    asm volatile("ldmatrix.sync.aligned.m8n8.x4.shared.b16 {%0,%1,%2,%3}, [%4];"
                 : "=r"(r[0]), "=r"(r[1]), "=r"(r[2]), "=r"(r[3]) : "r"(addr));
}

__device__ __forceinline__ void mma_f16(float c[4],
                                        uint32_t a0, uint32_t a1, uint32_t a2, uint32_t a3,
                                        uint32_t b0, uint32_t b1) {
    asm volatile(
        "mma.sync.aligned.m16n8k16.row.col.f32.f16.f16.f32 "
        "{%0,%1,%2,%3}, {%4,%5,%6,%7}, {%8,%9}, {%0,%1,%2,%3};\n"
        : "+f"(c[0]), "+f"(c[1]), "+f"(c[2]), "+f"(c[3])
        : "r"(a0), "r"(a1), "r"(a2), "r"(a3), "r"(b0), "r"(b1));
}

__device__ __forceinline__ float tanh_fast(float x) {
    float r;
    asm("tanh.approx.f32 %0, %1;" : "=f"(r) : "f"(x));
    return r;
}
__device__ __forceinline__ float sigmoid_fast(float x) {
    return fmaf(tanh_fast(0.5f * x), 0.5f, 0.5f);
}
__device__ __forceinline__ float sigmoidf_(float x) { return 1.0f / (1.0f + __expf(-x)); }

// =====================================================================
// Fused conversions: blocks [0,512) transpose Wp[:,0:2048] -> g_wh
// (fp16, [n][k]); blocks [512,2560) convert x -> g_xh (fp16), zero
// accumulation scratch, and preload d_out with b2.
// =====================================================================
__global__ void __launch_bounds__(256) conv_all_kernel(
    const float* __restrict__ x, const float* __restrict__ Wp,
    const float* __restrict__ b2, float* __restrict__ out) {
    __shared__ float tile[64][65];
    const int bid = blockIdx.x;
    const int tid = threadIdx.x;

    if (bid < 512) {
        // ---- W transpose tile ----
        int k0 = (bid & 15) * 64;
        int n0 = (bid >> 4) * 64;
#pragma unroll
        for (int i = 0; i < 16; i++) {
            int idx = tid + i * 256;
            int r = idx >> 6, c = idx & 63;
            tile[r][c] = Wp[(size_t)(k0 + r) * 3072 + n0 + c];
        }
        __syncthreads();
#pragma unroll
        for (int i = 0; i < 16; i++) {
            int idx = tid + i * 256;
            int r = idx >> 6, c = idx & 63;
            g_wh[(size_t)(n0 + r) * K_IN + k0 + c] = __float2half(tile[c][r]);
        }
        return;
    }

    // ---- x conversion ----
    const int cb = bid - 512;                    // 0..2047
    size_t n4 = (size_t)B_SZ * T_SZ * K_IN / 4;
    for (size_t i = (size_t)cb * 256 + tid; i < n4; i += (size_t)2048 * 256) {
        float4 v = ((const float4*)x)[i];
        __half2* o = (__half2*)g_xh;
        o[i * 2] = __floats2half2_rn(v.x, v.y);
        o[i * 2 + 1] = __floats2half2_rn(v.z, v.w);
    }
    int zi = cb * 256 + tid;
    if (zi < B_SZ * D_MODEL) g_opre[zi] = 0.0f;
    if (zi < B_SZ * MLP) { g_n0pre[zi] = 0.0f; g_n1pre[zi] = 0.0f; }
    if (zi < B_SZ * NCLS) out[zi] = b2[zi % NCLS];
}

// =====================================================================
// Fused fp16 mma.sync GEMM (round-11 pipeline: swizzled ldmatrix,
// 2-stage cp.async, loads before wait) + activations + chunk scan.
// Grid: (16 d-tiles, 256 bc). Block: 256 threads (8 warps, 2x4).
// =====================================================================
__global__ void __launch_bounds__(256)
gemm_scan_kernel(const float* __restrict__ bp) {
    extern __shared__ char smem[];
    const uint32_t sb = smem_u32(smem);

    const int dt = blockIdx.x;
    const int bc = blockIdx.y;
    const int b = bc >> 4;
    const int chunk = bc & 15;
    const int d0 = dt * 64;

    const int tid = threadIdx.x;
    const int lane = tid & 31;
    const int wid = tid >> 5;
    const int wm = (wid >> 2) * 64;       // warp m offset (0/64)
    const int wn = (wid & 3) * 32;        // warp n offset (0..96)
    const int g = lane >> 2;
    const int tg = lane & 3;

    const __half* xbase = g_xh + ((size_t)(b * T_SZ + chunk * BM)) * K_IN;

    float acc[4][4][4];
#pragma unroll
    for (int mi = 0; mi < 4; mi++)
#pragma unroll
        for (int ni = 0; ni < 4; ni++)
#pragma unroll
            for (int r = 0; r < 4; r++) acc[mi][ni][r] = 0.0f;

    // ldmatrix lane geometry (swizzled 128B rows)
    const int aRow = wm + (lane & 15);
    const int aHi = (lane >> 4) & 1;
    const int aSw = aRow & 7;
    const int bRow = wn + ((lane >> 4) & 1) * 8 + (lane & 7);
    const int bHi = (lane >> 3) & 1;
    const int bSw = lane & 7;

    auto load_stage = [&](int s, int kk) {
        uint32_t abase = sb + s * STAGE;
        uint32_t wbase = abase + ABYTES;
#pragma unroll
        for (int j = 0; j < 4; j++) {
            int idx = tid + j * 256;
            int r = idx >> 3, c8 = idx & 7;
            cpa16(abase + r * ROWB + ((c8 ^ (r & 7)) << 4),
                  xbase + (size_t)r * K_IN + kk + c8 * 8);
        }
#pragma unroll
        for (int j = 0; j < 4; j++) {
            int idx = tid + j * 256;
            int n = idx >> 3, c8 = idx & 7;
            int grow = (n < 64) ? (d0 + n) : (960 + d0 + n);
            cpa16(wbase + n * ROWB + ((c8 ^ (n & 7)) << 4),
                  g_wh + (size_t)grow * K_IN + kk + c8 * 8);
        }
        CP_COMMIT();
    };

    load_stage(0, 0);

    for (int i = 0; i < NCH; i++) {
        const int s = i & 1;
        if (i + 1 < NCH) {
            load_stage(s ^ 1, (i + 1) * BK);
            CP_WAIT(1);
        } else {
            CP_WAIT(0);
        }
        __syncthreads();

        const uint32_t stage = sb + s * STAGE;
        const uint32_t bstage = stage + ABYTES;
#pragma unroll
        for (int ks = 0; ks < BK / 16; ks++) {
            uint32_t a[4][4];
#pragma unroll
            for (int mi = 0; mi < 4; mi++)
                ldm4(a[mi], stage + (aRow + mi * 16) * ROWB +
                            ((((ks * 2 + aHi)) ^ aSw) << 4));
            uint32_t bb[4][2];
#pragma unroll
            for (int p = 0; p < 2; p++) {
                uint32_t r[4];
                ldm4(r, bstage + (bRow + p * 16) * ROWB +
                        ((((ks * 2 + bHi)) ^ bSw) << 4));
                bb[2 * p][0] = r[0]; bb[2 * p][1] = r[1];
                bb[2 * p + 1][0] = r[2]; bb[2 * p + 1][1] = r[3];
            }
#pragma unroll
            for (int mi = 0; mi < 4; mi++)
#pragma unroll
                for (int ni = 0; ni < 4; ni++)
                    mma_f16(acc[mi][ni], a[mi][0], a[mi][1], a[mi][2], a[mi][3],
                            bb[ni][0], bb[ni][1]);
        }
        __syncthreads();
    }

    // ---- epilogue: accumulators -> smem (f | z), then chunk scan ----
    float* fS = (float*)smem;                       // [128][EPITCH]
    float* zS = (float*)smem + 128 * EPITCH;        // [128][EPITCH]

#pragma unroll
    for (int mi = 0; mi < 4; mi++) {
#pragma unroll
        for (int ni = 0; ni < 4; ni++) {
            int nc = wn + ni * 8 + tg * 2;          // 0..126
            float* buf = (nc < 64) ? fS : zS;
            int col = nc & 63;
            int r = wm + mi * 16 + g;
            *(float2*)&buf[r * EPITCH + col] = make_float2(acc[mi][ni][0], acc[mi][ni][1]);
            *(float2*)&buf[(r + 8) * EPITCH + col] = make_float2(acc[mi][ni][2], acc[mi][ni][3]);
        }
    }
    __syncthreads();

    {
        const int dd = tid & 63;
        const int j = tid >> 6;                      // 4 t-subchunks of 32
        const float bpf = bp[d0 + dd];
        const float bpz = bp[D_MODEL + d0 + dd];
        float A = 1.0f, C = 0.0f;
#pragma unroll 4
        for (int t = j * 32; t < j * 32 + 32; t++) {
            float fh = fS[t * EPITCH + dd] + bpf;
            float zh = zS[t * EPITCH + dd] + bpz;
            float f = sigmoid_fast(fh);
            float z = (1.0f - f) * tanh_fast(zh);
            C = C * f + z;
            A = A * f;
        }
        __shared__ float s4A[4][64];
        __shared__ float s4C[4][64];
        s4A[j][dd] = A;
        s4C[j][dd] = C;
        __syncthreads();
        if (tid < 64) {
            float AA = s4A[0][tid], CC = s4C[0][tid];
#pragma unroll
            for (int jj = 1; jj < 4; jj++) {
                CC = CC * s4A[jj][tid] + s4C[jj][tid];
                AA = AA * s4A[jj][tid];
            }
            size_t o = ((size_t)b * NCHUNK + chunk) * D_MODEL + d0 + tid;
            g_chunkA[o] = AA;
            g_chunkC[o] = CC;
        }
    }
}

// =====================================================================
// Fused: h = (scan-combine) * sigmoid(opre + bp_o), then n0pre += h@W0.
// Each block recomputes its h slice from chunkA/C (L2-resident).
// Grid: (MLP/256 = 8, D_MODEL/32 = 32). Block 256.
// =====================================================================
__global__ void __launch_bounds__(256)
vmacc_h_kernel(const float* __restrict__ bp, const float* __restrict__ W0) {
    __shared__ float s_in[B_SZ * 32];
    const int tid = threadIdx.x;
    const int bn = blockIdx.x * 256;
    const int ks = blockIdx.y * 32;

    for (int i = tid; i < B_SZ * 32; i += 256) {
        int bb = i >> 5, k = i & 31;
        int kk = ks + k;
        float c = 0.0f;
#pragma unroll
        for (int ch = 0; ch < NCHUNK; ch++) {
            size_t o = ((size_t)bb * NCHUNK + ch) * D_MODEL + kk;
            c = c * g_chunkA[o] + g_chunkC[o];
        }
        float og = sigmoidf_(g_opre[bb * D_MODEL + kk] + bp[2 * D_MODEL + kk]);
        s_in[i] = c * og;
    }
    __syncthreads();

    int n = bn + tid;
    float acc[B_SZ];
#pragma unroll
    for (int bb = 0; bb < B_SZ; bb++) acc[bb] = 0.0f;

#pragma unroll 4
    for (int k = 0; k < 32; k++) {
        float w = W0[(size_t)(ks + k) * MLP + n];
#pragma unroll
        for (int bb = 0; bb < B_SZ; bb++) acc[bb] += s_in[bb * 32 + k] * w;
    }
#pragma unroll
    for (int bb = 0; bb < B_SZ; bb++) atomicAdd(&g_n0pre[(size_t)bb * MLP + n], acc[bb]);
}

// =====================================================================
// Tail: split-K vector(16) x matrix + atomicAdd.
// Optional bias+ReLU on the INPUT at load time.
// =====================================================================
#define KS 32
__global__ void __launch_bounds__(256)
vmacc_kernel(const float* __restrict__ in, size_t inStride,
             const float* __restrict__ inBias,      // nullptr = no act
             const float* __restrict__ W, int ldw, int colOff,
             float* __restrict__ pre, int K, int N) {
    __shared__ float s_in[B_SZ * KS];
    const int tid = threadIdx.x;
    const int bn = blockIdx.x * 256;
    const int ks = blockIdx.y * KS;

    for (int i = tid; i < B_SZ * KS; i += 256) {
        int bb = i / KS, k = i % KS;
        float v = in[(size_t)bb * inStride + ks + k];
        if (inBias) {
            v += inBias[ks + k];
            v = v > 0.0f ? v : 0.0f;
        }
        s_in[i] = v;
    }
    __syncthreads();

    int n = bn + tid;
    if (n >= N) return;

    float acc[B_SZ];
#pragma unroll
    for (int bb = 0; bb < B_SZ; bb++) acc[bb] = 0.0f;

#pragma unroll 4
    for (int k = 0; k < KS; k++) {
        float w = W[(size_t)(ks + k) * ldw + colOff + n];
#pragma unroll
        for (int bb = 0; bb < B_SZ; bb++) acc[bb] += s_in[bb * KS + k] * w;
    }
#pragma unroll
    for (int bb = 0; bb < B_SZ; bb++) atomicAdd(&pre[(size_t)bb * N + n], acc[bb]);
}

// =====================================================================
extern "C" void kernel_launch(void* const* d_in, const int* in_sizes, int n_in,
                              void* d_out, int out_size) {
    const float* x  = (const float*)d_in[0];
    const float* Wp = (const float*)d_in[1];
    const float* bp = (const float*)d_in[2];
    const float* W0 = (const float*)d_in[3];
    const float* b0 = (const float*)d_in[4];
    const float* W1 = (const float*)d_in[5];
    const float* b1 = (const float*)d_in[6];
    const float* W2 = (const float*)d_in[7];
    const float* b2 = (const float*)d_in[8];
    float* out = (float*)d_out;

    cudaFuncSetAttribute(gemm_scan_kernel,
                         cudaFuncAttributeMaxDynamicSharedMemorySize, SMEM_TOTAL);

    float *p_n0pre, *p_n1pre, *p_opre;
    cudaGetSymbolAddress((void**)&p_opre, g_opre);
    cudaGetSymbolAddress((void**)&p_n0pre, g_n0pre);
    cudaGetSymbolAddress((void**)&p_n1pre, g_n1pre);

    // 0. conversions + scratch zeroing + d_out=b2 (single kernel)
    conv_all_kernel<<<2560, 256>>>(x, Wp, b2, out);

    // 1. o-projection at t = T-1 (reads fp32 x directly)
    vmacc_kernel<<<dim3(D_MODEL / 256, K_IN / KS), 256>>>(
        x + (size_t)(T_SZ - 1) * K_IN, (size_t)T_SZ * K_IN, nullptr,
        Wp, 3 * D_MODEL, 2 * D_MODEL, p_opre, K_IN, D_MODEL);

    // 2. fused fp16 GEMM + chunk scan
    gemm_scan_kernel<<<dim3(16, B_SZ * NCHUNK), 256, SMEM_TOTAL>>>(bp);

    // 3. fused: combine chunks -> h -> n0pre = h @ W0
    vmacc_h_kernel<<<dim3(MLP / 256, D_MODEL / 32), 256>>>(bp, W0);

    // 4. MLP layer 1: n1pre = relu(n0pre + b0) @ W1   (act fused into load)
    vmacc_kernel<<<dim3(MLP / 256, MLP / KS), 256>>>(
        p_n0pre, MLP, b0, W1, MLP, 0, p_n1pre, MLP, MLP);

    // 5. output: out = b2 + relu(n1pre + b1) @ W2     (direct atomicAdd into d_out)
    vmacc_kernel<<<dim3((NCLS + 255) / 256, MLP / KS), 256>>>(
        p_n1pre, MLP, b1, W2, NCLS, 0, out, MLP, NCLS);
}

// round 16
// speedup vs baseline: 1.4175x; 1.0160x over previous
#include <cuda_runtime.h>
#include <cuda_fp16.h>
#include <cstdint>
#include <cstddef>

// ---------------- problem dims ----------------
#define B_SZ 16
#define T_SZ 2048
#define K_IN 1024
#define D_MODEL 1024
#define MLP 2048
#define NCLS 1000

// ---------------- GEMM tiling ----------------
#define BM 128               // t-rows per block (scan chunk)
#define BK 64                // k per pipeline chunk
#define NCH (K_IN / BK)      // 16
#define NCHUNK (T_SZ / BM)   // 16

#define ROWB 128                 // bytes per smem row (64 halves, swizzled)
#define ABYTES (BM * ROWB)       // 16384
#define STAGE (2 * ABYTES)       // 32768 (A + W)
#define EPITCH 66                // epilogue float pitch
#define SMEM_TOTAL (2 * 128 * EPITCH * 4)   // 67584 (> 2*STAGE = 65536)

// ---------------- scratch ----------------
__device__ __align__(16) __half g_xh[(size_t)B_SZ * T_SZ * K_IN];   // 64 MB
__device__ __align__(16) __half g_wh[2048 * K_IN];                  // 4 MB, [n][k]
__device__ float g_chunkA[B_SZ * NCHUNK * D_MODEL];
__device__ float g_chunkC[B_SZ * NCHUNK * D_MODEL];
__device__ float g_opre[B_SZ * D_MODEL];
__device__ float g_n0pre[B_SZ * MLP];
__device__ float g_n1pre[B_SZ * MLP];

// ---------------- helpers ----------------
__device__ __forceinline__ uint32_t smem_u32(const void* p) {
    uint32_t a;
    asm("{ .reg .u64 t; cvta.to.shared.u64 t, %1; cvt.u32.u64 %0, t; }" : "=r"(a) : "l"(p));
    return a;
}
__device__ __forceinline__ void cpa16(uint32_t dst, const void* src) {
    asm volatile("cp.async.cg.shared.global [%0], [%1], 16;\n" :: "r"(dst), "l"(src));
}
#define CP_COMMIT() asm volatile("cp.async.commit_group;" ::: "memory")
#define CP_WAIT(n) asm volatile("cp.async.wait_group %0;" :: "n"(n) : "memory")

__device__ __forceinline__ void ldm4(uint32_t r[4], uint32_t addr) {
    asm volatile("ldmatrix.sync.aligned.m8n8.x4.shared.b16 {%0,%1,%2,%3}, [%4];"
                 : "=r"(r[0]), "=r"(r[1]), "=r"(r[2]), "=r"(r[3]) : "r"(addr));
}

__device__ __forceinline__ void mma_f16(float c[4],
                                        uint32_t a0, uint32_t a1, uint32_t a2, uint32_t a3,
                                        uint32_t b0, uint32_t b1) {
    asm volatile(
        "mma.sync.aligned.m16n8k16.row.col.f32.f16.f16.f32 "
        "{%0,%1,%2,%3}, {%4,%5,%6,%7}, {%8,%9}, {%0,%1,%2,%3};\n"
        : "+f"(c[0]), "+f"(c[1]), "+f"(c[2]), "+f"(c[3])
        : "r"(a0), "r"(a1), "r"(a2), "r"(a3), "r"(b0), "r"(b1));
}

__device__ __forceinline__ float tanh_fast(float x) {
    float r;
    asm("tanh.approx.f32 %0, %1;" : "=f"(r) : "f"(x));
    return r;
}
__device__ __forceinline__ float sigmoid_fast(float x) {
    return fmaf(tanh_fast(0.5f * x), 0.5f, 0.5f);
}
__device__ __forceinline__ float sigmoidf_(float x) { return 1.0f / (1.0f + __expf(-x)); }

// =====================================================================
// Fused conversions: blocks [0,512) transpose Wp[:,0:2048] -> g_wh
// (fp16, [n][k]); blocks [512,2560) convert x -> g_xh (fp16), zero
// accumulation scratch, and preload d_out with b2.
// =====================================================================
__global__ void __launch_bounds__(256) conv_all_kernel(
    const float* __restrict__ x, const float* __restrict__ Wp,
    const float* __restrict__ b2, float* __restrict__ out) {
    __shared__ float tile[64][65];
    const int bid = blockIdx.x;
    const int tid = threadIdx.x;

    if (bid < 512) {
        // ---- W transpose tile ----
        int k0 = (bid & 15) * 64;
        int n0 = (bid >> 4) * 64;
#pragma unroll
        for (int i = 0; i < 16; i++) {
            int idx = tid + i * 256;
            int r = idx >> 6, c = idx & 63;
            tile[r][c] = Wp[(size_t)(k0 + r) * 3072 + n0 + c];
        }
        __syncthreads();
#pragma unroll
        for (int i = 0; i < 16; i++) {
            int idx = tid + i * 256;
            int r = idx >> 6, c = idx & 63;
            g_wh[(size_t)(n0 + r) * K_IN + k0 + c] = __float2half(tile[c][r]);
        }
        return;
    }

    // ---- x conversion ----
    const int cb = bid - 512;                    // 0..2047
    size_t n4 = (size_t)B_SZ * T_SZ * K_IN / 4;
    for (size_t i = (size_t)cb * 256 + tid; i < n4; i += (size_t)2048 * 256) {
        float4 v = ((const float4*)x)[i];
        __half2* o = (__half2*)g_xh;
        o[i * 2] = __floats2half2_rn(v.x, v.y);
        o[i * 2 + 1] = __floats2half2_rn(v.z, v.w);
    }
    int zi = cb * 256 + tid;
    if (zi < B_SZ * D_MODEL) g_opre[zi] = 0.0f;
    if (zi < B_SZ * MLP) { g_n0pre[zi] = 0.0f; g_n1pre[zi] = 0.0f; }
    if (zi < B_SZ * NCLS) out[zi] = b2[zi % NCLS];
}

// =====================================================================
// Fused fp16 mma.sync GEMM (round-11 pipeline: swizzled ldmatrix,
// 2-stage cp.async, loads before wait) + activations + chunk scan.
// Grid: (16 d-tiles, 256 bc). Block: 256 threads (8 warps, 2x4).
// =====================================================================
__global__ void __launch_bounds__(256)
gemm_scan_kernel(const float* __restrict__ bp) {
    extern __shared__ char smem[];
    const uint32_t sb = smem_u32(smem);

    const int dt = blockIdx.x;
    const int bc = blockIdx.y;
    const int b = bc >> 4;
    const int chunk = bc & 15;
    const int d0 = dt * 64;

    const int tid = threadIdx.x;
    const int lane = tid & 31;
    const int wid = tid >> 5;
    const int wm = (wid >> 2) * 64;       // warp m offset (0/64)
    const int wn = (wid & 3) * 32;        // warp n offset (0..96)
    const int g = lane >> 2;
    const int tg = lane & 3;

    const __half* xbase = g_xh + ((size_t)(b * T_SZ + chunk * BM)) * K_IN;

    float acc[4][4][4];
#pragma unroll
    for (int mi = 0; mi < 4; mi++)
#pragma unroll
        for (int ni = 0; ni < 4; ni++)
#pragma unroll
            for (int r = 0; r < 4; r++) acc[mi][ni][r] = 0.0f;

    // ldmatrix lane geometry (swizzled 128B rows)
    const int aRow = wm + (lane & 15);
    const int aHi = (lane >> 4) & 1;
    const int aSw = aRow & 7;
    const int bRow = wn + ((lane >> 4) & 1) * 8 + (lane & 7);
    const int bHi = (lane >> 3) & 1;
    const int bSw = lane & 7;

    auto load_stage = [&](int s, int kk) {
        uint32_t abase = sb + s * STAGE;
        uint32_t wbase = abase + ABYTES;
#pragma unroll
        for (int j = 0; j < 4; j++) {
            int idx = tid + j * 256;
            int r = idx >> 3, c8 = idx & 7;
            cpa16(abase + r * ROWB + ((c8 ^ (r & 7)) << 4),
                  xbase + (size_t)r * K_IN + kk + c8 * 8);
        }
#pragma unroll
        for (int j = 0; j < 4; j++) {
            int idx = tid + j * 256;
            int n = idx >> 3, c8 = idx & 7;
            int grow = (n < 64) ? (d0 + n) : (960 + d0 + n);
            cpa16(wbase + n * ROWB + ((c8 ^ (n & 7)) << 4),
                  g_wh + (size_t)grow * K_IN + kk + c8 * 8);
        }
        CP_COMMIT();
    };

    load_stage(0, 0);

    for (int i = 0; i < NCH; i++) {
        const int s = i & 1;
        if (i + 1 < NCH) {
            load_stage(s ^ 1, (i + 1) * BK);
            CP_WAIT(1);
        } else {
            CP_WAIT(0);
        }
        __syncthreads();

        const uint32_t stage = sb + s * STAGE;
        const uint32_t bstage = stage + ABYTES;
#pragma unroll
        for (int ks = 0; ks < BK / 16; ks++) {
            uint32_t a[4][4];
#pragma unroll
            for (int mi = 0; mi < 4; mi++)
                ldm4(a[mi], stage + (aRow + mi * 16) * ROWB +
                            ((((ks * 2 + aHi)) ^ aSw) << 4));
            uint32_t bb[4][2];
#pragma unroll
            for (int p = 0; p < 2; p++) {
                uint32_t r[4];
                ldm4(r, bstage + (bRow + p * 16) * ROWB +
                        ((((ks * 2 + bHi)) ^ bSw) << 4));
                bb[2 * p][0] = r[0]; bb[2 * p][1] = r[1];
                bb[2 * p + 1][0] = r[2]; bb[2 * p + 1][1] = r[3];
            }
#pragma unroll
            for (int mi = 0; mi < 4; mi++)
#pragma unroll
                for (int ni = 0; ni < 4; ni++)
                    mma_f16(acc[mi][ni], a[mi][0], a[mi][1], a[mi][2], a[mi][3],
                            bb[ni][0], bb[ni][1]);
        }
        __syncthreads();
    }

    // ---- epilogue: accumulators -> smem (f | z), then chunk scan ----
    float* fS = (float*)smem;                       // [128][EPITCH]
    float* zS = (float*)smem + 128 * EPITCH;        // [128][EPITCH]

#pragma unroll
    for (int mi = 0; mi < 4; mi++) {
#pragma unroll
        for (int ni = 0; ni < 4; ni++) {
            int nc = wn + ni * 8 + tg * 2;          // 0..126
            float* buf = (nc < 64) ? fS : zS;
            int col = nc & 63;
            int r = wm + mi * 16 + g;
            *(float2*)&buf[r * EPITCH + col] = make_float2(acc[mi][ni][0], acc[mi][ni][1]);
            *(float2*)&buf[(r + 8) * EPITCH + col] = make_float2(acc[mi][ni][2], acc[mi][ni][3]);
        }
    }
    __syncthreads();

    {
        const int dd = tid & 63;
        const int j = tid >> 6;                      // 4 t-subchunks of 32
        const float bpf = bp[d0 + dd];
        const float bpz = bp[D_MODEL + d0 + dd];
        float A = 1.0f, C = 0.0f;
#pragma unroll 4
        for (int t = j * 32; t < j * 32 + 32; t++) {
            float fh = fS[t * EPITCH + dd] + bpf;
            float zh = zS[t * EPITCH + dd] + bpz;
            float f = sigmoid_fast(fh);
            float z = (1.0f - f) * tanh_fast(zh);
            C = C * f + z;
            A = A * f;
        }
        __shared__ float s4A[4][64];
        __shared__ float s4C[4][64];
        s4A[j][dd] = A;
        s4C[j][dd] = C;
        __syncthreads();
        if (tid < 64) {
            float AA = s4A[0][tid], CC = s4C[0][tid];
#pragma unroll
            for (int jj = 1; jj < 4; jj++) {
                CC = CC * s4A[jj][tid] + s4C[jj][tid];
                AA = AA * s4A[jj][tid];
            }
            size_t o = ((size_t)b * NCHUNK + chunk) * D_MODEL + d0 + tid;
            g_chunkA[o] = AA;
            g_chunkC[o] = CC;
        }
    }
}

// =====================================================================
// Fused: h = (scan-combine) * sigmoid(opre + bp_o), then n0pre += h@W0.
// Grid: (MLP/256 = 8, D_MODEL/HKS = 64). Block 256.
// =====================================================================
#define HKS 16
__global__ void __launch_bounds__(256)
vmacc_h_kernel(const float* __restrict__ bp, const float* __restrict__ W0) {
    __shared__ float s_in[B_SZ * HKS];
    const int tid = threadIdx.x;
    const int bn = blockIdx.x * 256;
    const int ks = blockIdx.y * HKS;

    for (int i = tid; i < B_SZ * HKS; i += 256) {
        int bb = i / HKS, k = i % HKS;
        int kk = ks + k;
        float c = 0.0f;
#pragma unroll
        for (int ch = 0; ch < NCHUNK; ch++) {
            size_t o = ((size_t)bb * NCHUNK + ch) * D_MODEL + kk;
            c = c * g_chunkA[o] + g_chunkC[o];
        }
        float og = sigmoidf_(g_opre[bb * D_MODEL + kk] + bp[2 * D_MODEL + kk]);
        s_in[i] = c * og;
    }
    __syncthreads();

    int n = bn + tid;
    float acc[B_SZ];
#pragma unroll
    for (int bb = 0; bb < B_SZ; bb++) acc[bb] = 0.0f;

#pragma unroll
    for (int k = 0; k < HKS; k++) {
        float w = W0[(size_t)(ks + k) * MLP + n];
#pragma unroll
        for (int bb = 0; bb < B_SZ; bb++) acc[bb] += s_in[bb * HKS + k] * w;
    }
#pragma unroll
    for (int bb = 0; bb < B_SZ; bb++) atomicAdd(&g_n0pre[(size_t)bb * MLP + n], acc[bb]);
}

// =====================================================================
// Tail: split-K vector(16) x matrix + atomicAdd.
// Optional bias+ReLU on the INPUT at load time. KS as template param.
// =====================================================================
template <int TKS>
__global__ void __launch_bounds__(256)
vmacc_kernel(const float* __restrict__ in, size_t inStride,
             const float* __restrict__ inBias,      // nullptr = no act
             const float* __restrict__ W, int ldw, int colOff,
             float* __restrict__ pre, int N) {
    __shared__ float s_in[B_SZ * TKS];
    const int tid = threadIdx.x;
    const int bn = blockIdx.x * 256;
    const int ks = blockIdx.y * TKS;

    for (int i = tid; i < B_SZ * TKS; i += 256) {
        int bb = i / TKS, k = i % TKS;
        float v = in[(size_t)bb * inStride + ks + k];
        if (inBias) {
            v += inBias[ks + k];
            v = v > 0.0f ? v : 0.0f;
        }
        s_in[i] = v;
    }
    __syncthreads();

    int n = bn + tid;
    if (n >= N) return;

    float acc[B_SZ];
#pragma unroll
    for (int bb = 0; bb < B_SZ; bb++) acc[bb] = 0.0f;

#pragma unroll 8
    for (int k = 0; k < TKS; k++) {
        float w = W[(size_t)(ks + k) * ldw + colOff + n];
#pragma unroll
        for (int bb = 0; bb < B_SZ; bb++) acc[bb] += s_in[bb * TKS + k] * w;
    }
#pragma unroll
    for (int bb = 0; bb < B_SZ; bb++) atomicAdd(&pre[(size_t)bb * N + n], acc[bb]);
}

// =====================================================================
extern "C" void kernel_launch(void* const* d_in, const int* in_sizes, int n_in,
                              void* d_out, int out_size) {
    const float* x  = (const float*)d_in[0];
    const float* Wp = (const float*)d_in[1];
    const float* bp = (const float*)d_in[2];
    const float* W0 = (const float*)d_in[3];
    const float* b0 = (const float*)d_in[4];
    const float* W1 = (const float*)d_in[5];
    const float* b1 = (const float*)d_in[6];
    const float* W2 = (const float*)d_in[7];
    const float* b2 = (const float*)d_in[8];
    float* out = (float*)d_out;

    cudaFuncSetAttribute(gemm_scan_kernel,
                         cudaFuncAttributeMaxDynamicSharedMemorySize, SMEM_TOTAL);

    float *p_n0pre, *p_n1pre, *p_opre;
    cudaGetSymbolAddress((void**)&p_opre, g_opre);
    cudaGetSymbolAddress((void**)&p_n0pre, g_n0pre);
    cudaGetSymbolAddress((void**)&p_n1pre, g_n1pre);

    // 0. conversions + scratch zeroing + d_out=b2 (single kernel)
    conv_all_kernel<<<2560, 256>>>(x, Wp, b2, out);

    // 1. o-projection at t = T-1 (reads fp32 x directly)
    vmacc_kernel<16><<<dim3(D_MODEL / 256, K_IN / 16), 256>>>(
        x + (size_t)(T_SZ - 1) * K_IN, (size_t)T_SZ * K_IN, nullptr,
        Wp, 3 * D_MODEL, 2 * D_MODEL, p_opre, D_MODEL);

    // 2. fused fp16 GEMM + chunk scan
    gemm_scan_kernel<<<dim3(16, B_SZ * NCHUNK), 256, SMEM_TOTAL>>>(bp);

    // 3. fused: combine chunks -> h -> n0pre = h @ W0
    vmacc_h_kernel<<<dim3(MLP / 256, D_MODEL / HKS), 256>>>(bp, W0);

    // 4. MLP layer 1: n1pre = relu(n0pre + b0) @ W1   (act fused into load)
    vmacc_kernel<16><<<dim3(MLP / 256, MLP / 16), 256>>>(
        p_n0pre, MLP, b0, W1, MLP, 0, p_n1pre, MLP);

    // 5. output: out = b2 + relu(n1pre + b1) @ W2     (direct atomicAdd into d_out)
    vmacc_kernel<16><<<dim3((NCLS + 255) / 256, MLP / 16), 256>>>(
        p_n1pre, MLP, b1, W2, NCLS, 0, out, NCLS);
}

// round 17
// speedup vs baseline: 1.4296x; 1.0085x over previous
#include <cuda_runtime.h>
#include <cuda_fp16.h>
#include <cstdint>
#include <cstddef>

// ---------------- problem dims ----------------
#define B_SZ 16
#define T_SZ 2048
#define K_IN 1024
#define D_MODEL 1024
#define MLP 2048
#define NCLS 1000

// ---------------- GEMM tiling ----------------
#define BM 128               // t-rows per block (scan chunk)
#define BK 64                // k per pipeline chunk
#define NCH (K_IN / BK)      // 16
#define NCHUNK (T_SZ / BM)   // 16

#define ROWB 128                 // bytes per smem row (64 halves, swizzled)
#define ABYTES (BM * ROWB)       // 16384
#define STAGE (2 * ABYTES)       // 32768 (A + W)
#define EPITCH 66                // epilogue float pitch
#define SMEM_TOTAL (2 * 128 * EPITCH * 4)   // 67584 (> 2*STAGE = 65536)

// ---------------- scratch ----------------
__device__ __align__(16) __half g_xh[(size_t)B_SZ * T_SZ * K_IN];   // 64 MB
__device__ __align__(16) __half g_wh[2048 * K_IN];                  // 4 MB, [n][k]
__device__ float g_chunkA[B_SZ * NCHUNK * D_MODEL];
__device__ float g_chunkC[B_SZ * NCHUNK * D_MODEL];
__device__ float g_opre[B_SZ * D_MODEL];
__device__ float g_n0pre[B_SZ * MLP];
__device__ float g_n1pre[B_SZ * MLP];

// ---------------- helpers ----------------
__device__ __forceinline__ uint32_t smem_u32(const void* p) {
    uint32_t a;
    asm("{ .reg .u64 t; cvta.to.shared.u64 t, %1; cvt.u32.u64 %0, t; }" : "=r"(a) : "l"(p));
    return a;
}
__device__ __forceinline__ void cpa16(uint32_t dst, const void* src) {
    asm volatile("cp.async.cg.shared.global [%0], [%1], 16;\n" :: "r"(dst), "l"(src));
}
#define CP_COMMIT() asm volatile("cp.async.commit_group;" ::: "memory")
#define CP_WAIT(n) asm volatile("cp.async.wait_group %0;" :: "n"(n) : "memory")

__device__ __forceinline__ void ldm4(uint32_t r[4], uint32_t addr) {
    asm volatile("ldmatrix.sync.aligned.m8n8.x4.shared.b16 {%0,%1,%2,%3}, [%4];"
                 : "=r"(r[0]), "=r"(r[1]), "=r"(r[2]), "=r"(r[3]) : "r"(addr));
}

__device__ __forceinline__ void mma_f16(float c[4],
                                        uint32_t a0, uint32_t a1, uint32_t a2, uint32_t a3,
                                        uint32_t b0, uint32_t b1) {
    asm volatile(
        "mma.sync.aligned.m16n8k16.row.col.f32.f16.f16.f32 "
        "{%0,%1,%2,%3}, {%4,%5,%6,%7}, {%8,%9}, {%0,%1,%2,%3};\n"
        : "+f"(c[0]), "+f"(c[1]), "+f"(c[2]), "+f"(c[3])
        : "r"(a0), "r"(a1), "r"(a2), "r"(a3), "r"(b0), "r"(b1));
}

__device__ __forceinline__ float tanh_fast(float x) {
    float r;
    asm("tanh.approx.f32 %0, %1;" : "=f"(r) : "f"(x));
    return r;
}
__device__ __forceinline__ float sigmoid_fast(float x) {
    return fmaf(tanh_fast(0.5f * x), 0.5f, 0.5f);
}
__device__ __forceinline__ float sigmoidf_(float x) { return 1.0f / (1.0f + __expf(-x)); }

// =====================================================================
// Fused front kernel:
//   blocks [0,512)      : transpose Wp[:,0:2048] -> g_wh (fp16, [n][k])
//   blocks [512,2560)   : convert x -> g_xh (fp16), zero n0/n1 scratch,
//                         preload d_out with b2
//   blocks [2560,2816)  : o-projection at t=T-1 -> g_opre (atomicAdd;
//                         g_opre pre-zeroed by cudaMemsetAsync)
// =====================================================================
#define OKS 16
__global__ void __launch_bounds__(256) conv_all_kernel(
    const float* __restrict__ x, const float* __restrict__ Wp,
    const float* __restrict__ b2, float* __restrict__ out) {
    __shared__ float tile[64][65];
    __shared__ float s_in[B_SZ * OKS];
    const int bid = blockIdx.x;
    const int tid = threadIdx.x;

    if (bid < 512) {
        // ---- W transpose tile ----
        int k0 = (bid & 15) * 64;
        int n0 = (bid >> 4) * 64;
#pragma unroll
        for (int i = 0; i < 16; i++) {
            int idx = tid + i * 256;
            int r = idx >> 6, c = idx & 63;
            tile[r][c] = Wp[(size_t)(k0 + r) * 3072 + n0 + c];
        }
        __syncthreads();
#pragma unroll
        for (int i = 0; i < 16; i++) {
            int idx = tid + i * 256;
            int r = idx >> 6, c = idx & 63;
            g_wh[(size_t)(n0 + r) * K_IN + k0 + c] = __float2half(tile[c][r]);
        }
        return;
    }

    if (bid < 2560) {
        // ---- x conversion + scratch zero + out=b2 ----
        const int cb = bid - 512;                    // 0..2047
        size_t n4 = (size_t)B_SZ * T_SZ * K_IN / 4;
        for (size_t i = (size_t)cb * 256 + tid; i < n4; i += (size_t)2048 * 256) {
            float4 v = ((const float4*)x)[i];
            __half2* o = (__half2*)g_xh;
            o[i * 2] = __floats2half2_rn(v.x, v.y);
            o[i * 2 + 1] = __floats2half2_rn(v.z, v.w);
        }
        int zi = cb * 256 + tid;
        if (zi < B_SZ * MLP) { g_n0pre[zi] = 0.0f; g_n1pre[zi] = 0.0f; }
        if (zi < B_SZ * NCLS) out[zi] = b2[zi % NCLS];
        return;
    }

    // ---- o-projection (split-K vmacc into pre-zeroed g_opre) ----
    const int ob = bid - 2560;                       // 0..255
    const int bn = (ob & 3) * 256;                   // n tile
    const int ks = (ob >> 2) * OKS;                  // k chunk

    for (int i = tid; i < B_SZ * OKS; i += 256) {
        int bb = i / OKS, k = i % OKS;
        s_in[i] = x[((size_t)bb * T_SZ + (T_SZ - 1)) * K_IN + ks + k];
    }
    __syncthreads();

    int n = bn + tid;
    float acc[B_SZ];
#pragma unroll
    for (int bb = 0; bb < B_SZ; bb++) acc[bb] = 0.0f;
#pragma unroll
    for (int k = 0; k < OKS; k++) {
        float w = Wp[(size_t)(ks + k) * 3072 + 2 * D_MODEL + n];
#pragma unroll
        for (int bb = 0; bb < B_SZ; bb++) acc[bb] += s_in[bb * OKS + k] * w;
    }
#pragma unroll
    for (int bb = 0; bb < B_SZ; bb++) atomicAdd(&g_opre[(size_t)bb * D_MODEL + n], acc[bb]);
}

// =====================================================================
// Fused fp16 mma.sync GEMM (round-11 pipeline: swizzled ldmatrix,
// 2-stage cp.async, loads before wait) + activations + chunk scan.
// Grid: (16 d-tiles, 256 bc). Block: 256 threads (8 warps, 2x4).
// =====================================================================
__global__ void __launch_bounds__(256)
gemm_scan_kernel(const float* __restrict__ bp) {
    extern __shared__ char smem[];
    const uint32_t sb = smem_u32(smem);

    const int dt = blockIdx.x;
    const int bc = blockIdx.y;
    const int b = bc >> 4;
    const int chunk = bc & 15;
    const int d0 = dt * 64;

    const int tid = threadIdx.x;
    const int lane = tid & 31;
    const int wid = tid >> 5;
    const int wm = (wid >> 2) * 64;       // warp m offset (0/64)
    const int wn = (wid & 3) * 32;        // warp n offset (0..96)
    const int g = lane >> 2;
    const int tg = lane & 3;

    const __half* xbase = g_xh + ((size_t)(b * T_SZ + chunk * BM)) * K_IN;

    float acc[4][4][4];
#pragma unroll
    for (int mi = 0; mi < 4; mi++)
#pragma unroll
        for (int ni = 0; ni < 4; ni++)
#pragma unroll
            for (int r = 0; r < 4; r++) acc[mi][ni][r] = 0.0f;

    // ldmatrix lane geometry (swizzled 128B rows)
    const int aRow = wm + (lane & 15);
    const int aHi = (lane >> 4) & 1;
    const int aSw = aRow & 7;
    const int bRow = wn + ((lane >> 4) & 1) * 8 + (lane & 7);
    const int bHi = (lane >> 3) & 1;
    const int bSw = lane & 7;

    auto load_stage = [&](int s, int kk) {
        uint32_t abase = sb + s * STAGE;
        uint32_t wbase = abase + ABYTES;
#pragma unroll
        for (int j = 0; j < 4; j++) {
            int idx = tid + j * 256;
            int r = idx >> 3, c8 = idx & 7;
            cpa16(abase + r * ROWB + ((c8 ^ (r & 7)) << 4),
                  xbase + (size_t)r * K_IN + kk + c8 * 8);
        }
#pragma unroll
        for (int j = 0; j < 4; j++) {
            int idx = tid + j * 256;
            int n = idx >> 3, c8 = idx & 7;
            int grow = (n < 64) ? (d0 + n) : (960 + d0 + n);
            cpa16(wbase + n * ROWB + ((c8 ^ (n & 7)) << 4),
                  g_wh + (size_t)grow * K_IN + kk + c8 * 8);
        }
        CP_COMMIT();
    };

    load_stage(0, 0);

    for (int i = 0; i < NCH; i++) {
        const int s = i & 1;
        if (i + 1 < NCH) {
            load_stage(s ^ 1, (i + 1) * BK);
            CP_WAIT(1);
        } else {
            CP_WAIT(0);
        }
        __syncthreads();

        const uint32_t stage = sb + s * STAGE;
        const uint32_t bstage = stage + ABYTES;
#pragma unroll
        for (int ks = 0; ks < BK / 16; ks++) {
            uint32_t a[4][4];
#pragma unroll
            for (int mi = 0; mi < 4; mi++)
                ldm4(a[mi], stage + (aRow + mi * 16) * ROWB +
                            ((((ks * 2 + aHi)) ^ aSw) << 4));
            uint32_t bb[4][2];
#pragma unroll
            for (int p = 0; p < 2; p++) {
                uint32_t r[4];
                ldm4(r, bstage + (bRow + p * 16) * ROWB +
                        ((((ks * 2 + bHi)) ^ bSw) << 4));
                bb[2 * p][0] = r[0]; bb[2 * p][1] = r[1];
                bb[2 * p + 1][0] = r[2]; bb[2 * p + 1][1] = r[3];
            }
#pragma unroll
            for (int mi = 0; mi < 4; mi++)
#pragma unroll
                for (int ni = 0; ni < 4; ni++)
                    mma_f16(acc[mi][ni], a[mi][0], a[mi][1], a[mi][2], a[mi][3],
                            bb[ni][0], bb[ni][1]);
        }
        __syncthreads();
    }

    // ---- epilogue: accumulators -> smem (f | z), then chunk scan ----
    float* fS = (float*)smem;                       // [128][EPITCH]
    float* zS = (float*)smem + 128 * EPITCH;        // [128][EPITCH]

#pragma unroll
    for (int mi = 0; mi < 4; mi++) {
#pragma unroll
        for (int ni = 0; ni < 4; ni++) {
            int nc = wn + ni * 8 + tg * 2;          // 0..126
            float* buf = (nc < 64) ? fS : zS;
            int col = nc & 63;
            int r = wm + mi * 16 + g;
            *(float2*)&buf[r * EPITCH + col] = make_float2(acc[mi][ni][0], acc[mi][ni][1]);
            *(float2*)&buf[(r + 8) * EPITCH + col] = make_float2(acc[mi][ni][2], acc[mi][ni][3]);
        }
    }
    __syncthreads();

    {
        const int dd = tid & 63;
        const int j = tid >> 6;                      // 4 t-subchunks of 32
        const float bpf = bp[d0 + dd];
        const float bpz = bp[D_MODEL + d0 + dd];
        float A = 1.0f, C = 0.0f;
#pragma unroll 4
        for (int t = j * 32; t < j * 32 + 32; t++) {
            float fh = fS[t * EPITCH + dd] + bpf;
            float zh = zS[t * EPITCH + dd] + bpz;
            float f = sigmoid_fast(fh);
            float z = (1.0f - f) * tanh_fast(zh);
            C = C * f + z;
            A = A * f;
        }
        __shared__ float s4A[4][64];
        __shared__ float s4C[4][64];
        s4A[j][dd] = A;
        s4C[j][dd] = C;
        __syncthreads();
        if (tid < 64) {
            float AA = s4A[0][tid], CC = s4C[0][tid];
#pragma unroll
            for (int jj = 1; jj < 4; jj++) {
                CC = CC * s4A[jj][tid] + s4C[jj][tid];
                AA = AA * s4A[jj][tid];
            }
            size_t o = ((size_t)b * NCHUNK + chunk) * D_MODEL + d0 + tid;
            g_chunkA[o] = AA;
            g_chunkC[o] = CC;
        }
    }
}

// =====================================================================
// Fused: h = (scan-combine) * sigmoid(opre + bp_o), then n0pre += h@W0.
// Grid: (MLP/256 = 8, D_MODEL/HKS = 64). Block 256.
// =====================================================================
#define HKS 16
__global__ void __launch_bounds__(256)
vmacc_h_kernel(const float* __restrict__ bp, const float* __restrict__ W0) {
    __shared__ float s_in[B_SZ * HKS];
    const int tid = threadIdx.x;
    const int bn = blockIdx.x * 256;
    const int ks = blockIdx.y * HKS;

    for (int i = tid; i < B_SZ * HKS; i += 256) {
        int bb = i / HKS, k = i % HKS;
        int kk = ks + k;
        float c = 0.0f;
#pragma unroll
        for (int ch = 0; ch < NCHUNK; ch++) {
            size_t o = ((size_t)bb * NCHUNK + ch) * D_MODEL + kk;
            c = c * g_chunkA[o] + g_chunkC[o];
        }
        float og = sigmoidf_(g_opre[bb * D_MODEL + kk] + bp[2 * D_MODEL + kk]);
        s_in[i] = c * og;
    }
    __syncthreads();

    int n = bn + tid;
    float acc[B_SZ];
#pragma unroll
    for (int bb = 0; bb < B_SZ; bb++) acc[bb] = 0.0f;

#pragma unroll
    for (int k = 0; k < HKS; k++) {
        float w = W0[(size_t)(ks + k) * MLP + n];
#pragma unroll
        for (int bb = 0; bb < B_SZ; bb++) acc[bb] += s_in[bb * HKS + k] * w;
    }
#pragma unroll
    for (int bb = 0; bb < B_SZ; bb++) atomicAdd(&g_n0pre[(size_t)bb * MLP + n], acc[bb]);
}

// =====================================================================
// Tail: split-K vector(16) x matrix + atomicAdd.
// Optional bias+ReLU on the INPUT at load time. KS as template param.
// =====================================================================
template <int TKS>
__global__ void __launch_bounds__(256)
vmacc_kernel(const float* __restrict__ in, size_t inStride,
             const float* __restrict__ inBias,      // nullptr = no act
             const float* __restrict__ W, int ldw, int colOff,
             float* __restrict__ pre, int N) {
    __shared__ float s_in[B_SZ * TKS];
    const int tid = threadIdx.x;
    const int bn = blockIdx.x * 256;
    const int ks = blockIdx.y * TKS;

    for (int i = tid; i < B_SZ * TKS; i += 256) {
        int bb = i / TKS, k = i % TKS;
        float v = in[(size_t)bb * inStride + ks + k];
        if (inBias) {
            v += inBias[ks + k];
            v = v > 0.0f ? v : 0.0f;
        }
        s_in[i] = v;
    }
    __syncthreads();

    int n = bn + tid;
    if (n >= N) return;

    float acc[B_SZ];
#pragma unroll
    for (int bb = 0; bb < B_SZ; bb++) acc[bb] = 0.0f;

#pragma unroll 8
    for (int k = 0; k < TKS; k++) {
        float w = W[(size_t)(ks + k) * ldw + colOff + n];
#pragma unroll
        for (int bb = 0; bb < B_SZ; bb++) acc[bb] += s_in[bb * TKS + k] * w;
    }
#pragma unroll
    for (int bb = 0; bb < B_SZ; bb++) atomicAdd(&pre[(size_t)bb * N + n], acc[bb]);
}

// =====================================================================
extern "C" void kernel_launch(void* const* d_in, const int* in_sizes, int n_in,
                              void* d_out, int out_size) {
    const float* x  = (const float*)d_in[0];
    const float* Wp = (const float*)d_in[1];
    const float* bp = (const float*)d_in[2];
    const float* W0 = (const float*)d_in[3];
    const float* b0 = (const float*)d_in[4];
    const float* W1 = (const float*)d_in[5];
    const float* b1 = (const float*)d_in[6];
    const float* W2 = (const float*)d_in[7];
    const float* b2 = (const float*)d_in[8];
    float* out = (float*)d_out;

    cudaFuncSetAttribute(gemm_scan_kernel,
                         cudaFuncAttributeMaxDynamicSharedMemorySize, SMEM_TOTAL);

    float *p_n0pre, *p_n1pre, *p_opre;
    cudaGetSymbolAddress((void**)&p_opre, g_opre);
    cudaGetSymbolAddress((void**)&p_n0pre, g_n0pre);
    cudaGetSymbolAddress((void**)&p_n1pre, g_n1pre);

    // 0. zero the o-projection accumulator (must precede fused o-proj blocks)
    cudaMemsetAsync(p_opre, 0, B_SZ * D_MODEL * sizeof(float));

    // 1. conversions + scratch zeroing + d_out=b2 + o-projection (one kernel)
    conv_all_kernel<<<2816, 256>>>(x, Wp, b2, out);

    // 2. fused fp16 GEMM + chunk scan
    gemm_scan_kernel<<<dim3(16, B_SZ * NCHUNK), 256, SMEM_TOTAL>>>(bp);

    // 3. fused: combine chunks -> h -> n0pre = h @ W0
    vmacc_h_kernel<<<dim3(MLP / 256, D_MODEL / HKS), 256>>>(bp, W0);

    // 4. MLP layer 1: n1pre = relu(n0pre + b0) @ W1   (act fused into load)
    vmacc_kernel<16><<<dim3(MLP / 256, MLP / 16), 256>>>(
        p_n0pre, MLP, b0, W1, MLP, 0, p_n1pre, MLP);

    // 5. output: out = b2 + relu(n1pre + b1) @ W2     (direct atomicAdd into d_out)
    vmacc_kernel<16><<<dim3((NCLS + 255) / 256, MLP / 16), 256>>>(
        p_n1pre, MLP, b1, W2, NCLS, 0, out, NCLS);
}